// round 14
// baseline (speedup 1.0000x reference)
#include <cuda_runtime.h>
#include <cuda_bf16.h>
#include <math.h>
#include <stdint.h>

#define NM     1024
#define NA     32
#define ZD     64
#define HID    256
#define NT     10
#define NBOND  5
#define NEDGE  496
#define TOTA   32768
#define ATOM_OUT (TOTA*NT)

typedef unsigned long long ull;

__device__ __forceinline__ uint32_t smem_u32(const void* p) {
    uint32_t a;
    asm("{ .reg .u64 t; cvta.to.shared.u64 t, %1; cvt.u32.u64 %0, t; }" : "=r"(a) : "l"(p));
    return a;
}
__device__ __forceinline__ void ldmA(uint32_t* r, uint32_t a) {
    asm volatile("ldmatrix.sync.aligned.m8n8.x4.shared.b16 {%0,%1,%2,%3}, [%4];"
                 : "=r"(r[0]), "=r"(r[1]), "=r"(r[2]), "=r"(r[3]) : "r"(a));
}
__device__ __forceinline__ void ldmBt(uint32_t* r, uint32_t a) {
    asm volatile("ldmatrix.sync.aligned.m8n8.x4.trans.shared.b16 {%0,%1,%2,%3}, [%4];"
                 : "=r"(r[0]), "=r"(r[1]), "=r"(r[2]), "=r"(r[3]) : "r"(a));
}
__device__ __forceinline__ void ldmBt2(uint32_t* r, uint32_t a) {
    asm volatile("ldmatrix.sync.aligned.m8n8.x2.trans.shared.b16 {%0,%1}, [%2];"
                 : "=r"(r[0]), "=r"(r[1]) : "r"(a));
}
__device__ __forceinline__ void mma_bf16(float* c, const uint32_t* a, uint32_t b0, uint32_t b1) {
    asm volatile("mma.sync.aligned.m16n8k16.row.col.f32.bf16.bf16.f32 "
                 "{%0,%1,%2,%3},{%4,%5,%6,%7},{%8,%9},{%0,%1,%2,%3};"
                 : "+f"(c[0]), "+f"(c[1]), "+f"(c[2]), "+f"(c[3])
                 : "r"(a[0]), "r"(a[1]), "r"(a[2]), "r"(a[3]), "r"(b0), "r"(b1));
}
__device__ __forceinline__ float gelu_exact(float t) {
    return 0.5f*t*(1.f + erff(t*0.70710678118654752f));
}
__device__ __forceinline__ uint32_t bpack(float a, float b) {
    __nv_bfloat162 p(__float2bfloat16(a), __float2bfloat16(b));
    return *reinterpret_cast<uint32_t*>(&p);
}

// ---------------- device scratch ----------------
__device__ float g_Gpart[256*4096];
__device__ float g_spart[256*64];
__device__ float g_G[4096];
__device__ float g_s[64];
__device__ __align__(16) float g_A[HID];
__device__ __align__(16) float g_B[HID];
__device__ __nv_bfloat16 g_Wf_hi[NBOND*ZD*ZD];    // [td][c]
__device__ __nv_bfloat16 g_Wf_lo[NBOND*ZD*ZD];
__device__ __nv_bfloat16 g_z_hi[TOTA*ZD];
__device__ __nv_bfloat16 g_z_lo[TOTA*ZD];
__device__ __nv_bfloat16 g_W1h[ZD*HID];           // [c][j]
__device__ __nv_bfloat16 g_W1l[ZD*HID];

// ---------------- K1: prep (Wf split, z split) + partial Gram/colsum ----------------
__global__ void k_prep_stats(const float* __restrict__ z, const float* __restrict__ bm) {
    __shared__ float zs[128*68];
    int tid = threadIdx.x;
    int b = blockIdx.x;
    if (b >= 336) {                       // 512 z-split blocks
        size_t base = ((size_t)(b - 336)*256 + tid)*16;
#pragma unroll
        for (int r = 0; r < 4; r++) {
            float4 v = *(const float4*)(z + base + r*4);
            __nv_bfloat16 h0=__float2bfloat16(v.x), h1=__float2bfloat16(v.y),
                          h2=__float2bfloat16(v.z), h3=__float2bfloat16(v.w);
            __nv_bfloat16 l0=__float2bfloat16(v.x-__bfloat162float(h0));
            __nv_bfloat16 l1=__float2bfloat16(v.y-__bfloat162float(h1));
            __nv_bfloat16 l2=__float2bfloat16(v.z-__bfloat162float(h2));
            __nv_bfloat16 l3=__float2bfloat16(v.w-__bfloat162float(h3));
            __nv_bfloat162 hp0(h0,h1), hp1(h2,h3), lp0(l0,l1), lp1(l2,l3);
            uint2 hh = make_uint2(*(uint32_t*)&hp0, *(uint32_t*)&hp1);
            uint2 ll = make_uint2(*(uint32_t*)&lp0, *(uint32_t*)&lp1);
            *(uint2*)&g_z_hi[base + r*4] = hh;
            *(uint2*)&g_z_lo[base + r*4] = ll;
        }
        return;
    }
    if (b >= 256) {                       // 80 Wf-prep blocks
        int idx = (b - 256)*256 + tid;
        int td = idx >> 6, c = idx & 63;
        int t = td >> 6, d = td & 63;
        float val = 0.5f*(bm[(t<<12)+(d<<6)+c] + bm[(t<<12)+(c<<6)+d]);
        __nv_bfloat16 h = __float2bfloat16(val);
        g_Wf_hi[idx] = h;
        g_Wf_lo[idx] = __float2bfloat16(val - __bfloat162float(h));
        return;
    }
    const float* zp = z + b*(128*64);
    for (int idx = tid; idx < 128*64; idx += 256)
        zs[(idx>>6)*68 + (idx&63)] = zp[idx];
    __syncthreads();

    int i0 = (tid & 15) << 2;
    int j0 = (tid >> 4) << 2;
    float acc[16];
#pragma unroll
    for (int k = 0; k < 16; k++) acc[k] = 0.f;
#pragma unroll 2
    for (int r = 0; r < 128; r++) {
        float zi[4], zj[4];
#pragma unroll
        for (int x = 0; x < 4; x++) { zi[x] = zs[r*68 + i0 + x]; zj[x] = zs[r*68 + j0 + x]; }
#pragma unroll
        for (int x = 0; x < 4; x++)
#pragma unroll
            for (int y = 0; y < 4; y++)
                acc[x*4+y] += zi[x]*zj[y];
    }
    float* gp = g_Gpart + b*4096;
#pragma unroll
    for (int k = 0; k < 16; k++) gp[tid*16 + k] = acc[k];

    if (tid < 64) {
        float s = 0.f;
        for (int r = 0; r < 128; r++) s += zs[r*68 + tid];
        g_spart[b*64 + tid] = s;
    }
}

// ---------------- K2: reduction, 16 threads per element ----------------
__global__ void k_reduce() {
    __shared__ float red[1024];
    int t = threadIdx.x;
    int e = blockIdx.x*64 + (t & 63);
    int q = t >> 6;
    float s = 0.f;
    if (e < 4096) {
#pragma unroll 4
        for (int p = q*16; p < q*16 + 16; p++) s += g_Gpart[p*4096 + e];
    } else {
        int c = e - 4096;
#pragma unroll 4
        for (int p = q*16; p < q*16 + 16; p++) s += g_spart[p*64 + c];
    }
    red[t] = s;
    __syncthreads();
    if (t < 512) red[t] += red[t + 512];
    __syncthreads();
    if (t < 256) red[t] += red[t + 256];
    __syncthreads();
    if (t < 128) red[t] += red[t + 128];
    __syncthreads();
    if (t < 64) {
        float v = red[t] + red[t + 64];
        if (e < 4096) {
            int t16 = e >> 4, k = e & 15;
            int i = ((t16 & 15) << 2) + (k >> 2);
            int j = ((t16 >> 4) << 2) + (k & 3);
            g_G[i*64 + j] = v;
        } else {
            g_s[e - 4096] = v;
        }
    }
}

// ---------------- K3: analytic BN -> folded affine + W1 global split ----------------
__global__ void k_finalize(const float* __restrict__ W1, const float* __restrict__ b1,
                           const float* __restrict__ gamma, const float* __restrict__ beta) {
    __shared__ float Gs[4096], ssh[64], Wc[4][64];
    __shared__ float red1[256], red2[256];
    int tid = threadIdx.x;
    for (int i = tid; i < 4096; i += 256) Gs[i] = g_G[i];
    if (tid < 64) ssh[tid] = g_s[tid];
    int jq = tid >> 6, d = tid & 63;
    int j = blockIdx.x*4 + jq;
    float wdj = W1[d*HID + j];
    Wc[jq][d] = wdj;
    {
        __nv_bfloat16 h = __float2bfloat16(wdj);
        g_W1h[d*HID + j] = h;
        g_W1l[d*HID + j] = __float2bfloat16(wdj - __bfloat162float(h));
    }
    __syncthreads();

    float qv = 0.f;
#pragma unroll
    for (int c = 0; c < 64; c++) qv += Gs[d*64 + c] * Wc[jq][c];

    red1[tid] = ssh[d]*wdj;
    red2[tid] = qv*wdj;
    __syncthreads();
    for (int off = 32; off > 0; off >>= 1) {
        if (d < off) { red1[tid] += red1[tid+off]; red2[tid] += red2[tid+off]; }
        __syncthreads();
    }
    if (d == 0) {
        const float invN = 1.f/(float)TOTA;
        float sw = red1[tid], wGw = red2[tid];
        float bj = b1[j];
        float m1 = sw*invN + bj;
        float m2 = (wGw + 2.f*bj*sw)*invN + bj*bj;
        float var = m2 - m1*m1;
        float A = rsqrtf(var + 1e-5f) * gamma[j];
        g_A[j] = A;
        g_B[j] = (bj - m1)*A + beta[j];
    }
}

// ---------------- K4: all-MMA atoms kernel, 64 rows/block, 2 CTAs/SM (R13-identical) ----------------
#define KB_AH  0u
#define KB_AL  9216u
#define KB_BH  18432u
#define KB_BL  52224u
#define KB_W2H 86016u
#define KB_W2L 94208u
#define KB_GA  102400u
#define KB_GB  103424u
#define KB_TOT 104448

__global__ __launch_bounds__(256, 2)
void k_atoms_mma(const float* __restrict__ W2, const float* __restrict__ b2,
                 float* __restrict__ out) {
    extern __shared__ char smem[];
    uint32_t sb = smem_u32(smem);
    int tid = threadIdx.x, b = blockIdx.x;
    int lane = tid & 31, w = tid >> 5;

    const uint32_t* zh = (const uint32_t*)(g_z_hi + (size_t)b*4096);
    const uint32_t* zl = (const uint32_t*)(g_z_lo + (size_t)b*4096);
    for (int i = tid; i < 2048; i += 256) {
        int m = i >> 5, c2 = (i & 31)*2;
        *(uint32_t*)(smem + KB_AH + (m*72 + c2)*2) = zh[i];
        *(uint32_t*)(smem + KB_AL + (m*72 + c2)*2) = zl[i];
    }
    const uint32_t* wh = (const uint32_t*)g_W1h;
    const uint32_t* wl = (const uint32_t*)g_W1l;
    for (int i = tid; i < 8192; i += 256) {
        int c = i >> 7, j2 = (i & 127)*2;
        *(uint32_t*)(smem + KB_BH + (c*264 + j2)*2) = wh[i];
        *(uint32_t*)(smem + KB_BL + (c*264 + j2)*2) = wl[i];
    }
    for (int i = tid; i < 2048; i += 256) {
        *(uint32_t*)(smem + KB_W2H + i*4) = 0u;
        *(uint32_t*)(smem + KB_W2L + i*4) = 0u;
    }
    __syncthreads();
    for (int i = tid; i < 2560; i += 256) {
        int jj = i / 10, kk = i % 10;
        float v = W2[i];
        __nv_bfloat16 h = __float2bfloat16(v);
        *(__nv_bfloat16*)(smem + KB_W2H + (jj*16 + kk)*2) = h;
        *(__nv_bfloat16*)(smem + KB_W2L + (jj*16 + kk)*2) = __float2bfloat16(v - __bfloat162float(h));
    }
    float* gAs = (float*)(smem + KB_GA);
    float* gBs = (float*)(smem + KB_GB);
    if (tid < 256) { gAs[tid] = g_A[tid]; gBs[tid] = g_B[tid]; }
    __syncthreads();

    int mt = w & 3, nh = w >> 2;
    float acc[16][4];
#pragma unroll
    for (int i = 0; i < 16; i++)
#pragma unroll
        for (int x = 0; x < 4; x++) acc[i][x] = 0.f;

    uint32_t arow = (uint32_t)((mt*16 + (lane & 15))*72 + (lane >> 4)*8)*2;
    uint32_t bcol = (uint32_t)(nh*128 + (lane >> 4)*8)*2;
#pragma unroll
    for (int k = 0; k < 4; k++) {
        uint32_t ah[4], al[4];
        ldmA(ah, sb + KB_AH + arow + k*32);
        ldmA(al, sb + KB_AL + arow + k*32);
        uint32_t brow = (uint32_t)((k*16 + (lane & 15))*264)*2;
#pragma unroll
        for (int i = 0; i < 8; i++) {
            uint32_t bh[4], bl[4];
            ldmBt(bh, sb + KB_BH + brow + bcol + i*32);
            ldmBt(bl, sb + KB_BL + brow + bcol + i*32);
            mma_bf16(acc[2*i],   ah, bh[0], bh[1]);
            mma_bf16(acc[2*i+1], ah, bh[2], bh[3]);
            mma_bf16(acc[2*i],   al, bh[0], bh[1]);
            mma_bf16(acc[2*i+1], al, bh[2], bh[3]);
            mma_bf16(acc[2*i],   ah, bl[0], bl[1]);
            mma_bf16(acc[2*i+1], ah, bl[2], bl[3]);
        }
    }
    __syncthreads();

    int g = lane >> 2, tig = lane & 3;
#pragma unroll
    for (int a = 0; a < 16; a++) {
        int j0 = nh*128 + a*8 + 2*tig;
        float2 A2 = *(float2*)&gAs[j0];
        float2 B2 = *(float2*)&gBs[j0];
        acc[a][0] = gelu_exact(acc[a][0]*A2.x + B2.x);
        acc[a][1] = gelu_exact(acc[a][1]*A2.y + B2.y);
        acc[a][2] = gelu_exact(acc[a][2]*A2.x + B2.x);
        acc[a][3] = gelu_exact(acc[a][3]*A2.y + B2.y);
    }

    float acc2[2][4];
#pragma unroll
    for (int t = 0; t < 2; t++)
#pragma unroll
        for (int x = 0; x < 4; x++) acc2[t][x] = 0.f;

#pragma unroll
    for (int s = 0; s < 8; s++) {
        float v0 = acc[2*s][0],   v1 = acc[2*s][1],   v2 = acc[2*s][2],   v3 = acc[2*s][3];
        float u0 = acc[2*s+1][0], u1 = acc[2*s+1][1], u2 = acc[2*s+1][2], u3 = acc[2*s+1][3];
        uint32_t arh[4], arl[4];
        arh[0] = bpack(v0, v1); arh[1] = bpack(v2, v3);
        arh[2] = bpack(u0, u1); arh[3] = bpack(u2, u3);
        {
            __nv_bfloat162 h0 = *reinterpret_cast<__nv_bfloat162*>(&arh[0]);
            __nv_bfloat162 h1 = *reinterpret_cast<__nv_bfloat162*>(&arh[1]);
            __nv_bfloat162 h2 = *reinterpret_cast<__nv_bfloat162*>(&arh[2]);
            __nv_bfloat162 h3 = *reinterpret_cast<__nv_bfloat162*>(&arh[3]);
            arl[0] = bpack(v0 - __bfloat162float(h0.x), v1 - __bfloat162float(h0.y));
            arl[1] = bpack(v2 - __bfloat162float(h1.x), v3 - __bfloat162float(h1.y));
            arl[2] = bpack(u0 - __bfloat162float(h2.x), u1 - __bfloat162float(h2.y));
            arl[3] = bpack(u2 - __bfloat162float(h3.x), u3 - __bfloat162float(h3.y));
        }
        uint32_t baddr = (uint32_t)((nh*128 + s*16 + (lane & 15))*16 + (lane >> 4)*8)*2;
        uint32_t brh[4], brl[4];
        ldmBt(brh, sb + KB_W2H + baddr);
        ldmBt(brl, sb + KB_W2L + baddr);
        mma_bf16(acc2[0], arh, brh[0], brh[1]);
        mma_bf16(acc2[1], arh, brh[2], brh[3]);
        mma_bf16(acc2[0], arl, brh[0], brh[1]);
        mma_bf16(acc2[1], arl, brh[2], brh[3]);
        mma_bf16(acc2[0], arh, brl[0], brl[1]);
        mma_bf16(acc2[1], arh, brl[2], brl[3]);
    }

    float* P = (float*)smem;
    int row1 = mt*16 + g, row2 = row1 + 8;
    if (nh == 0) {
#pragma unroll
        for (int t = 0; t < 2; t++) {
            int col = t*8 + 2*tig;
            P[row1*16 + col]     = acc2[t][0];
            P[row1*16 + col + 1] = acc2[t][1];
            P[row2*16 + col]     = acc2[t][2];
            P[row2*16 + col + 1] = acc2[t][3];
        }
    }
    __syncthreads();
    if (nh == 1) {
#pragma unroll
        for (int t = 0; t < 2; t++) {
#pragma unroll
            for (int x = 0; x < 4; x++) {
                int col = t*8 + 2*tig + (x & 1);
                int row = (x < 2) ? row1 : row2;
                if (col < 10)
                    out[((size_t)b*64 + row)*10 + col] = acc2[t][x] + P[row*16 + col] + b2[col];
            }
        }
    }
}

// ---------------- K5: edges — 1 molecule/block, 256 thr, 2 CTAs/SM, Wf from global ----------------
// smem bf16 regions (strides: zT/Y 56 elems = 112 B, zA 72 elems = 144 B):
#define E2_ZTH 0u
#define E2_ZTL 7168u
#define E2_ZAH 14336u
#define E2_ZAL 18944u
#define E2_YH  23552u
#define E2_YL  59392u
#define E2_TOT 95232

__global__ __launch_bounds__(256, 2)
void k_edges_mma(float* __restrict__ out) {
    extern __shared__ char smem[];
    uint32_t sb = smem_u32(smem);
    int tid = threadIdx.x, mol = blockIdx.x;
    int lane = tid & 31, w = tid >> 5;
    int g16 = lane >> 2, tg2 = (lane & 3)*2;

    // ---- stage z (32 atoms): zA natural + zT transposed ----
    const uint32_t* zhw = (const uint32_t*)(g_z_hi + (size_t)mol*2048);
    const uint32_t* zlw = (const uint32_t*)(g_z_lo + (size_t)mol*2048);
    for (int i = tid; i < 1024; i += 256) {
        int a = i >> 5, c2 = (i & 31)*2;
        uint32_t vh = zhw[i], vl = zlw[i];
        *(uint32_t*)(smem + E2_ZAH + (a*72 + c2)*2) = vh;
        *(uint32_t*)(smem + E2_ZAL + (a*72 + c2)*2) = vl;
        __nv_bfloat162 hv = *reinterpret_cast<__nv_bfloat162*>(&vh);
        __nv_bfloat162 lv = *reinterpret_cast<__nv_bfloat162*>(&vl);
        *(__nv_bfloat16*)(smem + E2_ZTH + (c2*56 + a)*2)     = hv.x;
        *(__nv_bfloat16*)(smem + E2_ZTH + ((c2+1)*56 + a)*2) = hv.y;
        *(__nv_bfloat16*)(smem + E2_ZTL + (c2*56 + a)*2)     = lv.x;
        *(__nv_bfloat16*)(smem + E2_ZTL + ((c2+1)*56 + a)*2) = lv.y;
    }
    __syncthreads();

    // ---- Phase 1: Y[320][32] = Wf @ zT ; 40 m16n16 tiles, 5 per warp; A from GLOBAL ----
#pragma unroll
    for (int r = 0; r < 5; r++) {
        int idx = w*5 + r;                 // 0..39
        int mt = idx >> 1, nq = idx & 1;
        float acc[2][4];
#pragma unroll
        for (int t = 0; t < 2; t++)
#pragma unroll
            for (int x = 0; x < 4; x++) acc[t][x] = 0.f;

        int R = mt*16;
        uint32_t bcol = (uint32_t)(nq*16 + (lane>>4)*8)*2;
#pragma unroll
        for (int k = 0; k < 4; k++) {
            int C = k*16;
            uint32_t ah[4], al[4];
            ah[0] = *(const uint32_t*)&g_Wf_hi[(R+g16)*64   + C + tg2];
            ah[1] = *(const uint32_t*)&g_Wf_hi[(R+g16+8)*64 + C + tg2];
            ah[2] = *(const uint32_t*)&g_Wf_hi[(R+g16)*64   + C + 8 + tg2];
            ah[3] = *(const uint32_t*)&g_Wf_hi[(R+g16+8)*64 + C + 8 + tg2];
            al[0] = *(const uint32_t*)&g_Wf_lo[(R+g16)*64   + C + tg2];
            al[1] = *(const uint32_t*)&g_Wf_lo[(R+g16+8)*64 + C + tg2];
            al[2] = *(const uint32_t*)&g_Wf_lo[(R+g16)*64   + C + 8 + tg2];
            al[3] = *(const uint32_t*)&g_Wf_lo[(R+g16+8)*64 + C + 8 + tg2];
            uint32_t brow = (uint32_t)((k*16 + (lane&15))*56)*2;
            uint32_t bh[4], bl[4];
            ldmBt(bh, sb + E2_ZTH + brow + bcol);
            ldmBt(bl, sb + E2_ZTL + brow + bcol);
            mma_bf16(acc[0], ah, bh[0], bh[1]);
            mma_bf16(acc[1], ah, bh[2], bh[3]);
            mma_bf16(acc[0], al, bh[0], bh[1]);
            mma_bf16(acc[1], al, bh[2], bh[3]);
            mma_bf16(acc[0], ah, bl[0], bl[1]);
            mma_bf16(acc[1], ah, bl[2], bl[3]);
        }
        int gq = lane >> 2, tig = lane & 3;
#pragma unroll
        for (int t = 0; t < 2; t++) {
            int col = nq*16 + t*8 + 2*tig;
#pragma unroll
            for (int half = 0; half < 2; half++) {
                int row = mt*16 + gq + half*8;
                float v0 = acc[t][2*half], v1 = acc[t][2*half + 1];
                __nv_bfloat16 h0 = __float2bfloat16(v0), h1 = __float2bfloat16(v1);
                __nv_bfloat16 l0 = __float2bfloat16(v0 - __bfloat162float(h0));
                __nv_bfloat16 l1 = __float2bfloat16(v1 - __bfloat162float(h1));
                __nv_bfloat162 hp(h0, h1), lp(l0, l1);
                *(uint32_t*)(smem + E2_YH + (row*56 + col)*2) = *(uint32_t*)&hp;
                *(uint32_t*)(smem + E2_YL + (row*56 + col)*2) = *(uint32_t*)&lp;
            }
        }
    }
    __syncthreads();

    // ---- Phase 2: warp = (i-16-tile, j-8-tile); skip all-dead tiles ----
    {
        int mt2 = w >> 2, jn = w & 3;
        if (!(mt2 == 1 && jn < 2)) {       // tiles with i>=16 > j<16 produce nothing
            uint32_t ah[4][4], al[4][4];
            uint32_t off = (uint32_t)(((mt2*16 + (lane&15))*72 + (lane>>4)*8)*2);
#pragma unroll
            for (int k = 0; k < 4; k++) {
                ldmA(ah[k], sb + E2_ZAH + off + k*32);
                ldmA(al[k], sb + E2_ZAL + off + k*32);
            }
            float acc[5][4];
#pragma unroll
            for (int t = 0; t < 5; t++)
#pragma unroll
                for (int x = 0; x < 4; x++) acc[t][x] = 0.f;

            int jcol = jn*8;
#pragma unroll
            for (int t = 0; t < 5; t++) {
#pragma unroll
                for (int k = 0; k < 4; k++) {
                    uint32_t row = (uint32_t)(t*64 + k*16 + (lane & 15));
                    uint32_t bh[2], bl[2];
                    ldmBt2(bh, sb + E2_YH + (row*56 + jcol)*2);
                    ldmBt2(bl, sb + E2_YL + (row*56 + jcol)*2);
                    mma_bf16(acc[t], ah[k], bh[0], bh[1]);
                    mma_bf16(acc[t], al[k], bh[0], bh[1]);
                    mma_bf16(acc[t], ah[k], bl[0], bl[1]);
                }
            }

            int gq = lane >> 2, tig = lane & 3;
            float* eout = out + ATOM_OUT + (size_t)mol*(NEDGE*5);
#pragma unroll
            for (int pos = 0; pos < 4; pos++) {
                int i = mt2*16 + gq + (pos >> 1)*8;
                int j = jn*8 + 2*tig + (pos & 1);
                if (i < j) {
                    float v0 = acc[0][pos], v1 = acc[1][pos], v2 = acc[2][pos],
                          v3 = acc[3][pos], v4 = acc[4][pos];
                    float m = fmaxf(fmaxf(fmaxf(v0, v1), fmaxf(v2, v3)), v4);
                    float e0 = __expf(v0-m), e1 = __expf(v1-m), e2 = __expf(v2-m),
                          e3 = __expf(v3-m), e4 = __expf(v4-m);
                    float inv = 1.f/(e0+e1+e2+e3+e4);
                    int e = 31*i - (i*(i-1))/2 + (j - i - 1);
                    float* dst = eout + e*5;
                    dst[0] = e0*inv; dst[1] = e1*inv; dst[2] = e2*inv;
                    dst[3] = e3*inv; dst[4] = e4*inv;
                }
            }
        }
    }
}

// ---------------- launch ----------------
extern "C" void kernel_launch(void* const* d_in, const int* in_sizes, int n_in,
                              void* d_out, int out_size) {
    const float* z  = (const float*)d_in[0];
    const float* W1 = (const float*)d_in[1];
    const float* b1 = (const float*)d_in[2];
    const float* gm = (const float*)d_in[3];
    const float* bt = (const float*)d_in[4];
    const float* W2 = (const float*)d_in[5];
    const float* b2 = (const float*)d_in[6];
    const float* bm = (const float*)d_in[7];
    float* out = (float*)d_out;
    (void)in_sizes; (void)n_in; (void)out_size;

    cudaFuncSetAttribute(k_atoms_mma, cudaFuncAttributeMaxDynamicSharedMemorySize, KB_TOT);
    cudaFuncSetAttribute(k_edges_mma, cudaFuncAttributeMaxDynamicSharedMemorySize, E2_TOT);

    k_prep_stats<<<848, 256>>>(z, bm);
    k_reduce    <<<65,  1024>>>();
    k_finalize  <<<64,  256>>>(W1, b1, gm, bt);
    k_atoms_mma <<<512, 256, KB_TOT>>>(W2, b2, out);
    k_edges_mma <<<1024, 256, E2_TOT>>>(out);
}

// round 15
// speedup vs baseline: 1.1052x; 1.1052x over previous
#include <cuda_runtime.h>
#include <cuda_bf16.h>
#include <math.h>
#include <stdint.h>

#define NM     1024
#define NA     32
#define ZD     64
#define HID    256
#define NT     10
#define NBOND  5
#define NEDGE  496
#define TOTA   32768
#define ATOM_OUT (TOTA*NT)

typedef unsigned long long ull;

__device__ __forceinline__ uint32_t smem_u32(const void* p) {
    uint32_t a;
    asm("{ .reg .u64 t; cvta.to.shared.u64 t, %1; cvt.u32.u64 %0, t; }" : "=r"(a) : "l"(p));
    return a;
}
__device__ __forceinline__ void ldmA(uint32_t* r, uint32_t a) {
    asm volatile("ldmatrix.sync.aligned.m8n8.x4.shared.b16 {%0,%1,%2,%3}, [%4];"
                 : "=r"(r[0]), "=r"(r[1]), "=r"(r[2]), "=r"(r[3]) : "r"(a));
}
__device__ __forceinline__ void ldmBt(uint32_t* r, uint32_t a) {
    asm volatile("ldmatrix.sync.aligned.m8n8.x4.trans.shared.b16 {%0,%1,%2,%3}, [%4];"
                 : "=r"(r[0]), "=r"(r[1]), "=r"(r[2]), "=r"(r[3]) : "r"(a));
}
__device__ __forceinline__ void ldmBt2(uint32_t* r, uint32_t a) {
    asm volatile("ldmatrix.sync.aligned.m8n8.x2.trans.shared.b16 {%0,%1}, [%2];"
                 : "=r"(r[0]), "=r"(r[1]) : "r"(a));
}
__device__ __forceinline__ void mma_bf16(float* c, const uint32_t* a, uint32_t b0, uint32_t b1) {
    asm volatile("mma.sync.aligned.m16n8k16.row.col.f32.bf16.bf16.f32 "
                 "{%0,%1,%2,%3},{%4,%5,%6,%7},{%8,%9},{%0,%1,%2,%3};"
                 : "+f"(c[0]), "+f"(c[1]), "+f"(c[2]), "+f"(c[3])
                 : "r"(a[0]), "r"(a[1]), "r"(a[2]), "r"(a[3]), "r"(b0), "r"(b1));
}
__device__ __forceinline__ float gelu_exact(float t) {
    return 0.5f*t*(1.f + erff(t*0.70710678118654752f));
}
__device__ __forceinline__ uint32_t bpack(float a, float b) {
    __nv_bfloat162 p(__float2bfloat16(a), __float2bfloat16(b));
    return *reinterpret_cast<uint32_t*>(&p);
}

// ---------------- device scratch ----------------
__device__ float g_Gpart[256*4096];
__device__ float g_spart[256*64];
__device__ float g_G[4096];
__device__ float g_s[64];
__device__ __align__(16) float g_A[HID];
__device__ __align__(16) float g_B[HID];
__device__ __nv_bfloat16 g_Wf_hi[NBOND*ZD*ZD];    // [td][c]
__device__ __nv_bfloat16 g_Wf_lo[NBOND*ZD*ZD];
__device__ __nv_bfloat16 g_z_hi[TOTA*ZD];
__device__ __nv_bfloat16 g_z_lo[TOTA*ZD];
__device__ __nv_bfloat16 g_W1h[ZD*HID];           // [c][j]
__device__ __nv_bfloat16 g_W1l[ZD*HID];

// ---------------- K1: prep (Wf split, z split) + partial Gram/colsum ----------------
__global__ void k_prep_stats(const float* __restrict__ z, const float* __restrict__ bm) {
    __shared__ float zs[128*68];
    int tid = threadIdx.x;
    int b = blockIdx.x;
    if (b >= 336) {                       // 512 z-split blocks
        size_t base = ((size_t)(b - 336)*256 + tid)*16;
#pragma unroll
        for (int r = 0; r < 4; r++) {
            float4 v = *(const float4*)(z + base + r*4);
            __nv_bfloat16 h0=__float2bfloat16(v.x), h1=__float2bfloat16(v.y),
                          h2=__float2bfloat16(v.z), h3=__float2bfloat16(v.w);
            __nv_bfloat16 l0=__float2bfloat16(v.x-__bfloat162float(h0));
            __nv_bfloat16 l1=__float2bfloat16(v.y-__bfloat162float(h1));
            __nv_bfloat16 l2=__float2bfloat16(v.z-__bfloat162float(h2));
            __nv_bfloat16 l3=__float2bfloat16(v.w-__bfloat162float(h3));
            __nv_bfloat162 hp0(h0,h1), hp1(h2,h3), lp0(l0,l1), lp1(l2,l3);
            uint2 hh = make_uint2(*(uint32_t*)&hp0, *(uint32_t*)&hp1);
            uint2 ll = make_uint2(*(uint32_t*)&lp0, *(uint32_t*)&lp1);
            *(uint2*)&g_z_hi[base + r*4] = hh;
            *(uint2*)&g_z_lo[base + r*4] = ll;
        }
        return;
    }
    if (b >= 256) {                       // 80 Wf-prep blocks
        int idx = (b - 256)*256 + tid;
        int td = idx >> 6, c = idx & 63;
        int t = td >> 6, d = td & 63;
        float val = 0.5f*(bm[(t<<12)+(d<<6)+c] + bm[(t<<12)+(c<<6)+d]);
        __nv_bfloat16 h = __float2bfloat16(val);
        g_Wf_hi[idx] = h;
        g_Wf_lo[idx] = __float2bfloat16(val - __bfloat162float(h));
        return;
    }
    const float* zp = z + b*(128*64);
    for (int idx = tid; idx < 128*64; idx += 256)
        zs[(idx>>6)*68 + (idx&63)] = zp[idx];
    __syncthreads();

    int i0 = (tid & 15) << 2;
    int j0 = (tid >> 4) << 2;
    float acc[16];
#pragma unroll
    for (int k = 0; k < 16; k++) acc[k] = 0.f;
#pragma unroll 2
    for (int r = 0; r < 128; r++) {
        float zi[4], zj[4];
#pragma unroll
        for (int x = 0; x < 4; x++) { zi[x] = zs[r*68 + i0 + x]; zj[x] = zs[r*68 + j0 + x]; }
#pragma unroll
        for (int x = 0; x < 4; x++)
#pragma unroll
            for (int y = 0; y < 4; y++)
                acc[x*4+y] += zi[x]*zj[y];
    }
    float* gp = g_Gpart + b*4096;
#pragma unroll
    for (int k = 0; k < 16; k++) gp[tid*16 + k] = acc[k];

    if (tid < 64) {
        float s = 0.f;
        for (int r = 0; r < 128; r++) s += zs[r*68 + tid];
        g_spart[b*64 + tid] = s;
    }
}

// ---------------- K2: reduction, 16 threads per element ----------------
__global__ void k_reduce() {
    __shared__ float red[1024];
    int t = threadIdx.x;
    int e = blockIdx.x*64 + (t & 63);
    int q = t >> 6;
    float s = 0.f;
    if (e < 4096) {
#pragma unroll 4
        for (int p = q*16; p < q*16 + 16; p++) s += g_Gpart[p*4096 + e];
    } else {
        int c = e - 4096;
#pragma unroll 4
        for (int p = q*16; p < q*16 + 16; p++) s += g_spart[p*64 + c];
    }
    red[t] = s;
    __syncthreads();
    if (t < 512) red[t] += red[t + 512];
    __syncthreads();
    if (t < 256) red[t] += red[t + 256];
    __syncthreads();
    if (t < 128) red[t] += red[t + 128];
    __syncthreads();
    if (t < 64) {
        float v = red[t] + red[t + 64];
        if (e < 4096) {
            int t16 = e >> 4, k = e & 15;
            int i = ((t16 & 15) << 2) + (k >> 2);
            int j = ((t16 >> 4) << 2) + (k & 3);
            g_G[i*64 + j] = v;
        } else {
            g_s[e - 4096] = v;
        }
    }
}

// ---------------- K3: analytic BN -> folded affine + W1 global split ----------------
__global__ void k_finalize(const float* __restrict__ W1, const float* __restrict__ b1,
                           const float* __restrict__ gamma, const float* __restrict__ beta) {
    __shared__ float Gs[4096], ssh[64], Wc[4][64];
    __shared__ float red1[256], red2[256];
    int tid = threadIdx.x;
    for (int i = tid; i < 4096; i += 256) Gs[i] = g_G[i];
    if (tid < 64) ssh[tid] = g_s[tid];
    int jq = tid >> 6, d = tid & 63;
    int j = blockIdx.x*4 + jq;
    float wdj = W1[d*HID + j];
    Wc[jq][d] = wdj;
    {
        __nv_bfloat16 h = __float2bfloat16(wdj);
        g_W1h[d*HID + j] = h;
        g_W1l[d*HID + j] = __float2bfloat16(wdj - __bfloat162float(h));
    }
    __syncthreads();

    float qv = 0.f;
#pragma unroll
    for (int c = 0; c < 64; c++) qv += Gs[d*64 + c] * Wc[jq][c];

    red1[tid] = ssh[d]*wdj;
    red2[tid] = qv*wdj;
    __syncthreads();
    for (int off = 32; off > 0; off >>= 1) {
        if (d < off) { red1[tid] += red1[tid+off]; red2[tid] += red2[tid+off]; }
        __syncthreads();
    }
    if (d == 0) {
        const float invN = 1.f/(float)TOTA;
        float sw = red1[tid], wGw = red2[tid];
        float bj = b1[j];
        float m1 = sw*invN + bj;
        float m2 = (wGw + 2.f*bj*sw)*invN + bj*bj;
        float var = m2 - m1*m1;
        float A = rsqrtf(var + 1e-5f) * gamma[j];
        g_A[j] = A;
        g_B[j] = (bj - m1)*A + beta[j];
    }
}

// ---------------- K4: all-MMA atoms kernel, 64 rows/block, 2 CTAs/SM ----------------
#define KB_AH  0u
#define KB_AL  9216u
#define KB_BH  18432u
#define KB_BL  52224u
#define KB_W2H 86016u
#define KB_W2L 94208u
#define KB_GA  102400u
#define KB_GB  103424u
#define KB_TOT 104448

__global__ __launch_bounds__(256, 2)
void k_atoms_mma(const float* __restrict__ W2, const float* __restrict__ b2,
                 float* __restrict__ out) {
    extern __shared__ char smem[];
    uint32_t sb = smem_u32(smem);
    int tid = threadIdx.x, b = blockIdx.x;
    int lane = tid & 31, w = tid >> 5;

    const uint32_t* zh = (const uint32_t*)(g_z_hi + (size_t)b*4096);
    const uint32_t* zl = (const uint32_t*)(g_z_lo + (size_t)b*4096);
    for (int i = tid; i < 2048; i += 256) {
        int m = i >> 5, c2 = (i & 31)*2;
        *(uint32_t*)(smem + KB_AH + (m*72 + c2)*2) = zh[i];
        *(uint32_t*)(smem + KB_AL + (m*72 + c2)*2) = zl[i];
    }
    const uint32_t* wh = (const uint32_t*)g_W1h;
    const uint32_t* wl = (const uint32_t*)g_W1l;
    for (int i = tid; i < 8192; i += 256) {
        int c = i >> 7, j2 = (i & 127)*2;
        *(uint32_t*)(smem + KB_BH + (c*264 + j2)*2) = wh[i];
        *(uint32_t*)(smem + KB_BL + (c*264 + j2)*2) = wl[i];
    }
    for (int i = tid; i < 2048; i += 256) {
        *(uint32_t*)(smem + KB_W2H + i*4) = 0u;
        *(uint32_t*)(smem + KB_W2L + i*4) = 0u;
    }
    __syncthreads();
    for (int i = tid; i < 2560; i += 256) {
        int jj = i / 10, kk = i % 10;
        float v = W2[i];
        __nv_bfloat16 h = __float2bfloat16(v);
        *(__nv_bfloat16*)(smem + KB_W2H + (jj*16 + kk)*2) = h;
        *(__nv_bfloat16*)(smem + KB_W2L + (jj*16 + kk)*2) = __float2bfloat16(v - __bfloat162float(h));
    }
    float* gAs = (float*)(smem + KB_GA);
    float* gBs = (float*)(smem + KB_GB);
    if (tid < 256) { gAs[tid] = g_A[tid]; gBs[tid] = g_B[tid]; }
    __syncthreads();

    int mt = w & 3, nh = w >> 2;
    float acc[16][4];
#pragma unroll
    for (int i = 0; i < 16; i++)
#pragma unroll
        for (int x = 0; x < 4; x++) acc[i][x] = 0.f;

    uint32_t arow = (uint32_t)((mt*16 + (lane & 15))*72 + (lane >> 4)*8)*2;
    uint32_t bcol = (uint32_t)(nh*128 + (lane >> 4)*8)*2;
#pragma unroll
    for (int k = 0; k < 4; k++) {
        uint32_t ah[4], al[4];
        ldmA(ah, sb + KB_AH + arow + k*32);
        ldmA(al, sb + KB_AL + arow + k*32);
        uint32_t brow = (uint32_t)((k*16 + (lane & 15))*264)*2;
#pragma unroll
        for (int i = 0; i < 8; i++) {
            uint32_t bh[4], bl[4];
            ldmBt(bh, sb + KB_BH + brow + bcol + i*32);
            ldmBt(bl, sb + KB_BL + brow + bcol + i*32);
            mma_bf16(acc[2*i],   ah, bh[0], bh[1]);
            mma_bf16(acc[2*i+1], ah, bh[2], bh[3]);
            mma_bf16(acc[2*i],   al, bh[0], bh[1]);
            mma_bf16(acc[2*i+1], al, bh[2], bh[3]);
            mma_bf16(acc[2*i],   ah, bl[0], bl[1]);
            mma_bf16(acc[2*i+1], ah, bl[2], bl[3]);
        }
    }
    __syncthreads();

    int g = lane >> 2, tig = lane & 3;
#pragma unroll
    for (int a = 0; a < 16; a++) {
        int j0 = nh*128 + a*8 + 2*tig;
        float2 A2 = *(float2*)&gAs[j0];
        float2 B2 = *(float2*)&gBs[j0];
        acc[a][0] = gelu_exact(acc[a][0]*A2.x + B2.x);
        acc[a][1] = gelu_exact(acc[a][1]*A2.y + B2.y);
        acc[a][2] = gelu_exact(acc[a][2]*A2.x + B2.x);
        acc[a][3] = gelu_exact(acc[a][3]*A2.y + B2.y);
    }

    float acc2[2][4];
#pragma unroll
    for (int t = 0; t < 2; t++)
#pragma unroll
        for (int x = 0; x < 4; x++) acc2[t][x] = 0.f;

#pragma unroll
    for (int s = 0; s < 8; s++) {
        float v0 = acc[2*s][0],   v1 = acc[2*s][1],   v2 = acc[2*s][2],   v3 = acc[2*s][3];
        float u0 = acc[2*s+1][0], u1 = acc[2*s+1][1], u2 = acc[2*s+1][2], u3 = acc[2*s+1][3];
        uint32_t arh[4], arl[4];
        arh[0] = bpack(v0, v1); arh[1] = bpack(v2, v3);
        arh[2] = bpack(u0, u1); arh[3] = bpack(u2, u3);
        {
            __nv_bfloat162 h0 = *reinterpret_cast<__nv_bfloat162*>(&arh[0]);
            __nv_bfloat162 h1 = *reinterpret_cast<__nv_bfloat162*>(&arh[1]);
            __nv_bfloat162 h2 = *reinterpret_cast<__nv_bfloat162*>(&arh[2]);
            __nv_bfloat162 h3 = *reinterpret_cast<__nv_bfloat162*>(&arh[3]);
            arl[0] = bpack(v0 - __bfloat162float(h0.x), v1 - __bfloat162float(h0.y));
            arl[1] = bpack(v2 - __bfloat162float(h1.x), v3 - __bfloat162float(h1.y));
            arl[2] = bpack(u0 - __bfloat162float(h2.x), u1 - __bfloat162float(h2.y));
            arl[3] = bpack(u2 - __bfloat162float(h3.x), u3 - __bfloat162float(h3.y));
        }
        uint32_t baddr = (uint32_t)((nh*128 + s*16 + (lane & 15))*16 + (lane >> 4)*8)*2;
        uint32_t brh[4], brl[4];
        ldmBt(brh, sb + KB_W2H + baddr);
        ldmBt(brl, sb + KB_W2L + baddr);
        mma_bf16(acc2[0], arh, brh[0], brh[1]);
        mma_bf16(acc2[1], arh, brh[2], brh[3]);
        mma_bf16(acc2[0], arl, brh[0], brh[1]);
        mma_bf16(acc2[1], arl, brh[2], brh[3]);
        mma_bf16(acc2[0], arh, brl[0], brl[1]);
        mma_bf16(acc2[1], arh, brl[2], brl[3]);
    }

    float* P = (float*)smem;
    int row1 = mt*16 + g, row2 = row1 + 8;
    if (nh == 0) {
#pragma unroll
        for (int t = 0; t < 2; t++) {
            int col = t*8 + 2*tig;
            P[row1*16 + col]     = acc2[t][0];
            P[row1*16 + col + 1] = acc2[t][1];
            P[row2*16 + col]     = acc2[t][2];
            P[row2*16 + col + 1] = acc2[t][3];
        }
    }
    __syncthreads();
    if (nh == 1) {
#pragma unroll
        for (int t = 0; t < 2; t++) {
#pragma unroll
            for (int x = 0; x < 4; x++) {
                int col = t*8 + 2*tig + (x & 1);
                int row = (x < 2) ? row1 : row2;
                if (col < 10)
                    out[((size_t)b*64 + row)*10 + col] = acc2[t][x] + P[row*16 + col] + b2[col];
            }
        }
    }
}

// ---------------- K5: edges via mma.sync (R13 structure + dead-tile skip) ----------------
#define EG_WFH 0u
#define EG_WFL 46080u
#define EG_ZTH 92160u
#define EG_ZTL 101376u
#define EG_ZAH 110592u
#define EG_ZAL 119808u
#define EG_YH  129024u
#define EG_YL  175104u
#define EG_TOT 221184

__global__ __launch_bounds__(512, 1)
void k_edges_mma(float* __restrict__ out) {
    extern __shared__ char smem[];
    uint32_t sb = smem_u32(smem);
    int tid = threadIdx.x, b = blockIdx.x;
    int lane = tid & 31, w = tid >> 5;

    for (int it = tid; it < 10240; it += 512) {
        int td = it >> 5, c2 = (it & 31)*2;
        uint32_t vh = *(const uint32_t*)&g_Wf_hi[td*64 + c2];
        uint32_t vl = *(const uint32_t*)&g_Wf_lo[td*64 + c2];
        *(uint32_t*)(smem + EG_WFH + (td*72 + c2)*2) = vh;
        *(uint32_t*)(smem + EG_WFL + (td*72 + c2)*2) = vl;
    }
    const __nv_bfloat16* zh = g_z_hi + (size_t)b*4096;
    const __nv_bfloat16* zl = g_z_lo + (size_t)b*4096;
    for (int it = tid; it < 2048; it += 512) {
        int a = it >> 5, c2 = (it & 31)*2;
        uint32_t vh = *(const uint32_t*)&zh[a*64 + c2];
        uint32_t vl = *(const uint32_t*)&zl[a*64 + c2];
        *(uint32_t*)(smem + EG_ZAH + (a*72 + c2)*2) = vh;
        *(uint32_t*)(smem + EG_ZAL + (a*72 + c2)*2) = vl;
        __nv_bfloat162 hv = *reinterpret_cast<__nv_bfloat162*>(&vh);
        __nv_bfloat162 lv = *reinterpret_cast<__nv_bfloat162*>(&vl);
        *(__nv_bfloat16*)(smem + EG_ZTH + (c2*72 + a)*2)     = hv.x;
        *(__nv_bfloat16*)(smem + EG_ZTH + ((c2+1)*72 + a)*2) = hv.y;
        *(__nv_bfloat16*)(smem + EG_ZTL + (c2*72 + a)*2)     = lv.x;
        *(__nv_bfloat16*)(smem + EG_ZTL + ((c2+1)*72 + a)*2) = lv.y;
    }
    __syncthreads();

    // ---- Phase 1: Y[320][64] = Wf @ zT ; 80 m16n16 tiles, exactly 5 per warp ----
#pragma unroll
    for (int r = 0; r < 5; r++) {
        int idx = w*5 + r;
        int mt = idx >> 2, nq = idx & 3;
        float acc[2][4];
#pragma unroll
        for (int t = 0; t < 2; t++)
#pragma unroll
            for (int x = 0; x < 4; x++) acc[t][x] = 0.f;

        uint32_t arow = (uint32_t)((mt*16 + (lane&15))*72 + (lane>>4)*8)*2;
        uint32_t bcol = (uint32_t)(nq*16 + (lane>>4)*8)*2;
#pragma unroll
        for (int k = 0; k < 4; k++) {
            uint32_t ah[4], al[4];
            ldmA(ah, sb + EG_WFH + arow + k*32);
            ldmA(al, sb + EG_WFL + arow + k*32);
            uint32_t brow = (uint32_t)((k*16 + (lane&15))*72)*2;
            uint32_t bh[4], bl[4];
            ldmBt(bh, sb + EG_ZTH + brow + bcol);
            ldmBt(bl, sb + EG_ZTL + brow + bcol);
            mma_bf16(acc[0], ah, bh[0], bh[1]);
            mma_bf16(acc[1], ah, bh[2], bh[3]);
            mma_bf16(acc[0], al, bh[0], bh[1]);
            mma_bf16(acc[1], al, bh[2], bh[3]);
            mma_bf16(acc[0], ah, bl[0], bl[1]);
            mma_bf16(acc[1], ah, bl[2], bl[3]);
        }
        int g = lane >> 2, tig = lane & 3;
#pragma unroll
        for (int t = 0; t < 2; t++) {
            int col = nq*16 + t*8 + 2*tig;
#pragma unroll
            for (int half = 0; half < 2; half++) {
                int row = mt*16 + g + half*8;
                float v0 = acc[t][2*half], v1 = acc[t][2*half + 1];
                __nv_bfloat16 h0 = __float2bfloat16(v0), h1 = __float2bfloat16(v1);
                __nv_bfloat16 l0 = __float2bfloat16(v0 - __bfloat162float(h0));
                __nv_bfloat16 l1 = __float2bfloat16(v1 - __bfloat162float(h1));
                __nv_bfloat162 hp(h0, h1), lp(l0, l1);
                *(uint32_t*)(smem + EG_YH + (row*72 + col)*2) = *(uint32_t*)&hp;
                *(uint32_t*)(smem + EG_YL + (row*72 + col)*2) = *(uint32_t*)&lp;
            }
        }
    }
    __syncthreads();

    // ---- Phase 2: warp = (molh, i-16-tile, j-8-tile); skip all-dead tiles ----
    {
        int molh = w >> 3, mt2 = (w >> 2) & 1, jn = w & 3;
        if (!(mt2 == 1 && jn < 2)) {       // i in [16,32) x j < 16: fully below diagonal
            uint32_t ah[4][4], al[4][4];
            uint32_t off = (uint32_t)(((molh*32 + mt2*16 + (lane&15))*72 + (lane>>4)*8)*2);
#pragma unroll
            for (int k = 0; k < 4; k++) {
                ldmA(ah[k], sb + EG_ZAH + off + k*32);
                ldmA(al[k], sb + EG_ZAL + off + k*32);
            }
            float acc[5][4];
#pragma unroll
            for (int t = 0; t < 5; t++)
#pragma unroll
                for (int x = 0; x < 4; x++) acc[t][x] = 0.f;

            int jcol = molh*32 + jn*8;
#pragma unroll
            for (int t = 0; t < 5; t++) {
#pragma unroll
                for (int k = 0; k < 4; k++) {
                    uint32_t row = (uint32_t)(t*64 + k*16 + (lane & 15));
                    uint32_t bh[2], bl[2];
                    ldmBt2(bh, sb + EG_YH + (row*72 + jcol)*2);
                    ldmBt2(bl, sb + EG_YL + (row*72 + jcol)*2);
                    mma_bf16(acc[t], ah[k], bh[0], bh[1]);
                    mma_bf16(acc[t], al[k], bh[0], bh[1]);
                    mma_bf16(acc[t], ah[k], bl[0], bl[1]);
                }
            }

            int g = lane >> 2, tig = lane & 3;
            int mol = b*2 + molh;
            float* eout = out + ATOM_OUT + mol*(NEDGE*5);
#pragma unroll
            for (int pos = 0; pos < 4; pos++) {
                int i = mt2*16 + g + (pos >> 1)*8;
                int j = jn*8 + 2*tig + (pos & 1);
                if (i < j) {
                    float v0 = acc[0][pos], v1 = acc[1][pos], v2 = acc[2][pos],
                          v3 = acc[3][pos], v4 = acc[4][pos];
                    float m = fmaxf(fmaxf(fmaxf(v0, v1), fmaxf(v2, v3)), v4);
                    float e0 = __expf(v0-m), e1 = __expf(v1-m), e2 = __expf(v2-m),
                          e3 = __expf(v3-m), e4 = __expf(v4-m);
                    float inv = 1.f/(e0+e1+e2+e3+e4);
                    int e = 31*i - (i*(i-1))/2 + (j - i - 1);
                    float* dst = eout + e*5;
                    dst[0] = e0*inv; dst[1] = e1*inv; dst[2] = e2*inv;
                    dst[3] = e3*inv; dst[4] = e4*inv;
                }
            }
        }
    }
}

// ---------------- launch ----------------
extern "C" void kernel_launch(void* const* d_in, const int* in_sizes, int n_in,
                              void* d_out, int out_size) {
    const float* z  = (const float*)d_in[0];
    const float* W1 = (const float*)d_in[1];
    const float* b1 = (const float*)d_in[2];
    const float* gm = (const float*)d_in[3];
    const float* bt = (const float*)d_in[4];
    const float* W2 = (const float*)d_in[5];
    const float* b2 = (const float*)d_in[6];
    const float* bm = (const float*)d_in[7];
    float* out = (float*)d_out;
    (void)in_sizes; (void)n_in; (void)out_size;

    cudaFuncSetAttribute(k_atoms_mma, cudaFuncAttributeMaxDynamicSharedMemorySize, KB_TOT);
    cudaFuncSetAttribute(k_edges_mma, cudaFuncAttributeMaxDynamicSharedMemorySize, EG_TOT);

    k_prep_stats<<<848, 256>>>(z, bm);
    k_reduce    <<<65,  1024>>>();
    k_finalize  <<<64,  256>>>(W1, b1, gm, bt);
    k_atoms_mma <<<512, 256, KB_TOT>>>(W2, b2, out);
    k_edges_mma <<<512, 512, EG_TOT>>>(out);
}

// round 16
// speedup vs baseline: 1.1090x; 1.0035x over previous
#include <cuda_runtime.h>
#include <cuda_bf16.h>
#include <math.h>
#include <stdint.h>

#define NM     1024
#define NA     32
#define ZD     64
#define HID    256
#define NT     10
#define NBOND  5
#define NEDGE  496
#define TOTA   32768
#define ATOM_OUT (TOTA*NT)

typedef unsigned long long ull;

__device__ __forceinline__ uint32_t smem_u32(const void* p) {
    uint32_t a;
    asm("{ .reg .u64 t; cvta.to.shared.u64 t, %1; cvt.u32.u64 %0, t; }" : "=r"(a) : "l"(p));
    return a;
}
__device__ __forceinline__ void ldmA(uint32_t* r, uint32_t a) {
    asm volatile("ldmatrix.sync.aligned.m8n8.x4.shared.b16 {%0,%1,%2,%3}, [%4];"
                 : "=r"(r[0]), "=r"(r[1]), "=r"(r[2]), "=r"(r[3]) : "r"(a));
}
__device__ __forceinline__ void ldmBt(uint32_t* r, uint32_t a) {
    asm volatile("ldmatrix.sync.aligned.m8n8.x4.trans.shared.b16 {%0,%1,%2,%3}, [%4];"
                 : "=r"(r[0]), "=r"(r[1]), "=r"(r[2]), "=r"(r[3]) : "r"(a));
}
__device__ __forceinline__ void ldmBt2(uint32_t* r, uint32_t a) {
    asm volatile("ldmatrix.sync.aligned.m8n8.x2.trans.shared.b16 {%0,%1}, [%2];"
                 : "=r"(r[0]), "=r"(r[1]) : "r"(a));
}
__device__ __forceinline__ void mma_bf16(float* c, const uint32_t* a, uint32_t b0, uint32_t b1) {
    asm volatile("mma.sync.aligned.m16n8k16.row.col.f32.bf16.bf16.f32 "
                 "{%0,%1,%2,%3},{%4,%5,%6,%7},{%8,%9},{%0,%1,%2,%3};"
                 : "+f"(c[0]), "+f"(c[1]), "+f"(c[2]), "+f"(c[3])
                 : "r"(a[0]), "r"(a[1]), "r"(a[2]), "r"(a[3]), "r"(b0), "r"(b1));
}
// single-instruction pack: lo half <- a, hi half <- b (rn rounding, matches __float2bfloat16)
__device__ __forceinline__ uint32_t bpack(float a, float b) {
    uint32_t r;
    asm("cvt.rn.bf16x2.f32 %0, %1, %2;" : "=r"(r) : "f"(b), "f"(a));
    return r;
}
// split a float pair into bf16x2 hi + bf16x2 lo-residual (self-consistent)
__device__ __forceinline__ void split2(float v0, float v1, uint32_t& hi, uint32_t& lo) {
    hi = bpack(v0, v1);
    __nv_bfloat162 h = *reinterpret_cast<__nv_bfloat162*>(&hi);
    lo = bpack(v0 - __bfloat162float(h.x), v1 - __bfloat162float(h.y));
}
// A&S 7.1.26 erf approximation, max abs err 1.5e-7
__device__ __forceinline__ float erf_fast(float x) {
    float ax = fabsf(x);
    float d  = fmaf(0.3275911f, ax, 1.0f);
    float t;
    asm("rcp.approx.f32 %0, %1;" : "=f"(t) : "f"(d));
    float p = fmaf(1.061405429f, t, -1.453152027f);
    p = fmaf(p, t, 1.421413741f);
    p = fmaf(p, t, -0.284496736f);
    p = fmaf(p, t, 0.254829592f);
    float e = __expf(-ax*ax);
    float r = 1.0f - p*t*e;
    return copysignf(r, x);
}
__device__ __forceinline__ float gelu_exact(float t) {
    return 0.5f*t*(1.f + erf_fast(t*0.70710678118654752f));
}

// ---------------- device scratch ----------------
__device__ float g_Gpart[256*4096];
__device__ float g_spart[256*64];
__device__ float g_G[4096];
__device__ float g_s[64];
__device__ __align__(16) float g_A[HID];
__device__ __align__(16) float g_B[HID];
__device__ __nv_bfloat16 g_Wf_hi[NBOND*ZD*ZD];    // [td][c]
__device__ __nv_bfloat16 g_Wf_lo[NBOND*ZD*ZD];
__device__ __nv_bfloat16 g_z_hi[TOTA*ZD];
__device__ __nv_bfloat16 g_z_lo[TOTA*ZD];
__device__ __nv_bfloat16 g_W1h[ZD*HID];           // [c][j]
__device__ __nv_bfloat16 g_W1l[ZD*HID];

// ---------------- K1: prep (Wf split, z split) + partial Gram/colsum ----------------
__global__ void k_prep_stats(const float* __restrict__ z, const float* __restrict__ bm) {
    __shared__ float zs[128*68];
    int tid = threadIdx.x;
    int b = blockIdx.x;
    if (b >= 336) {                       // 512 z-split blocks
        size_t base = ((size_t)(b - 336)*256 + tid)*16;
#pragma unroll
        for (int r = 0; r < 4; r++) {
            float4 v = *(const float4*)(z + base + r*4);
            uint32_t h01, l01, h23, l23;
            split2(v.x, v.y, h01, l01);
            split2(v.z, v.w, h23, l23);
            *(uint2*)&g_z_hi[base + r*4] = make_uint2(h01, h23);
            *(uint2*)&g_z_lo[base + r*4] = make_uint2(l01, l23);
        }
        return;
    }
    if (b >= 256) {                       // 80 Wf-prep blocks
        int idx = (b - 256)*256 + tid;
        int td = idx >> 6, c = idx & 63;
        int t = td >> 6, d = td & 63;
        float val = 0.5f*(bm[(t<<12)+(d<<6)+c] + bm[(t<<12)+(c<<6)+d]);
        __nv_bfloat16 h = __float2bfloat16(val);
        g_Wf_hi[idx] = h;
        g_Wf_lo[idx] = __float2bfloat16(val - __bfloat162float(h));
        return;
    }
    const float* zp = z + b*(128*64);
    for (int idx = tid; idx < 128*64; idx += 256)
        zs[(idx>>6)*68 + (idx&63)] = zp[idx];
    __syncthreads();

    int i0 = (tid & 15) << 2;
    int j0 = (tid >> 4) << 2;
    float acc[16];
#pragma unroll
    for (int k = 0; k < 16; k++) acc[k] = 0.f;
#pragma unroll 2
    for (int r = 0; r < 128; r++) {
        float zi[4], zj[4];
#pragma unroll
        for (int x = 0; x < 4; x++) { zi[x] = zs[r*68 + i0 + x]; zj[x] = zs[r*68 + j0 + x]; }
#pragma unroll
        for (int x = 0; x < 4; x++)
#pragma unroll
            for (int y = 0; y < 4; y++)
                acc[x*4+y] += zi[x]*zj[y];
    }
    float* gp = g_Gpart + b*4096;
#pragma unroll
    for (int k = 0; k < 16; k++) gp[tid*16 + k] = acc[k];

    if (tid < 64) {
        float s = 0.f;
        for (int r = 0; r < 128; r++) s += zs[r*68 + tid];
        g_spart[b*64 + tid] = s;
    }
}

// ---------------- K2: reduction, 16 threads per element ----------------
__global__ void k_reduce() {
    __shared__ float red[1024];
    int t = threadIdx.x;
    int e = blockIdx.x*64 + (t & 63);
    int q = t >> 6;
    float s = 0.f;
    if (e < 4096) {
#pragma unroll 4
        for (int p = q*16; p < q*16 + 16; p++) s += g_Gpart[p*4096 + e];
    } else {
        int c = e - 4096;
#pragma unroll 4
        for (int p = q*16; p < q*16 + 16; p++) s += g_spart[p*64 + c];
    }
    red[t] = s;
    __syncthreads();
    if (t < 512) red[t] += red[t + 512];
    __syncthreads();
    if (t < 256) red[t] += red[t + 256];
    __syncthreads();
    if (t < 128) red[t] += red[t + 128];
    __syncthreads();
    if (t < 64) {
        float v = red[t] + red[t + 64];
        if (e < 4096) {
            int t16 = e >> 4, k = e & 15;
            int i = ((t16 & 15) << 2) + (k >> 2);
            int j = ((t16 >> 4) << 2) + (k & 3);
            g_G[i*64 + j] = v;
        } else {
            g_s[e - 4096] = v;
        }
    }
}

// ---------------- K3: analytic BN -> folded affine + W1 global split ----------------
__global__ void k_finalize(const float* __restrict__ W1, const float* __restrict__ b1,
                           const float* __restrict__ gamma, const float* __restrict__ beta) {
    __shared__ float Gs[4096], ssh[64], Wc[4][64];
    __shared__ float red1[256], red2[256];
    int tid = threadIdx.x;
    for (int i = tid; i < 4096; i += 256) Gs[i] = g_G[i];
    if (tid < 64) ssh[tid] = g_s[tid];
    int jq = tid >> 6, d = tid & 63;
    int j = blockIdx.x*4 + jq;
    float wdj = W1[d*HID + j];
    Wc[jq][d] = wdj;
    {
        __nv_bfloat16 h = __float2bfloat16(wdj);
        g_W1h[d*HID + j] = h;
        g_W1l[d*HID + j] = __float2bfloat16(wdj - __bfloat162float(h));
    }
    __syncthreads();

    float qv = 0.f;
#pragma unroll
    for (int c = 0; c < 64; c++) qv += Gs[d*64 + c] * Wc[jq][c];

    red1[tid] = ssh[d]*wdj;
    red2[tid] = qv*wdj;
    __syncthreads();
    for (int off = 32; off > 0; off >>= 1) {
        if (d < off) { red1[tid] += red1[tid+off]; red2[tid] += red2[tid+off]; }
        __syncthreads();
    }
    if (d == 0) {
        const float invN = 1.f/(float)TOTA;
        float sw = red1[tid], wGw = red2[tid];
        float bj = b1[j];
        float m1 = sw*invN + bj;
        float m2 = (wGw + 2.f*bj*sw)*invN + bj*bj;
        float var = m2 - m1*m1;
        float A = rsqrtf(var + 1e-5f) * gamma[j];
        g_A[j] = A;
        g_B[j] = (bj - m1)*A + beta[j];
    }
}

// ---------------- K4: all-MMA atoms kernel, 64 rows/block, 2 CTAs/SM ----------------
#define KB_AH  0u
#define KB_AL  9216u
#define KB_BH  18432u
#define KB_BL  52224u
#define KB_W2H 86016u
#define KB_W2L 94208u
#define KB_GA  102400u
#define KB_GB  103424u
#define KB_TOT 104448

__global__ __launch_bounds__(256, 2)
void k_atoms_mma(const float* __restrict__ W2, const float* __restrict__ b2,
                 float* __restrict__ out) {
    extern __shared__ char smem[];
    uint32_t sb = smem_u32(smem);
    int tid = threadIdx.x, b = blockIdx.x;
    int lane = tid & 31, w = tid >> 5;

    const uint32_t* zh = (const uint32_t*)(g_z_hi + (size_t)b*4096);
    const uint32_t* zl = (const uint32_t*)(g_z_lo + (size_t)b*4096);
    for (int i = tid; i < 2048; i += 256) {
        int m = i >> 5, c2 = (i & 31)*2;
        *(uint32_t*)(smem + KB_AH + (m*72 + c2)*2) = zh[i];
        *(uint32_t*)(smem + KB_AL + (m*72 + c2)*2) = zl[i];
    }
    const uint32_t* wh = (const uint32_t*)g_W1h;
    const uint32_t* wl = (const uint32_t*)g_W1l;
    for (int i = tid; i < 8192; i += 256) {
        int c = i >> 7, j2 = (i & 127)*2;
        *(uint32_t*)(smem + KB_BH + (c*264 + j2)*2) = wh[i];
        *(uint32_t*)(smem + KB_BL + (c*264 + j2)*2) = wl[i];
    }
    for (int i = tid; i < 2048; i += 256) {
        *(uint32_t*)(smem + KB_W2H + i*4) = 0u;
        *(uint32_t*)(smem + KB_W2L + i*4) = 0u;
    }
    __syncthreads();
    for (int i = tid; i < 2560; i += 256) {
        int jj = i / 10, kk = i % 10;
        float v = W2[i];
        __nv_bfloat16 h = __float2bfloat16(v);
        *(__nv_bfloat16*)(smem + KB_W2H + (jj*16 + kk)*2) = h;
        *(__nv_bfloat16*)(smem + KB_W2L + (jj*16 + kk)*2) = __float2bfloat16(v - __bfloat162float(h));
    }
    float* gAs = (float*)(smem + KB_GA);
    float* gBs = (float*)(smem + KB_GB);
    if (tid < 256) { gAs[tid] = g_A[tid]; gBs[tid] = g_B[tid]; }
    __syncthreads();

    int mt = w & 3, nh = w >> 2;
    float acc[16][4];
#pragma unroll
    for (int i = 0; i < 16; i++)
#pragma unroll
        for (int x = 0; x < 4; x++) acc[i][x] = 0.f;

    uint32_t arow = (uint32_t)((mt*16 + (lane & 15))*72 + (lane >> 4)*8)*2;
    uint32_t bcol = (uint32_t)(nh*128 + (lane >> 4)*8)*2;
#pragma unroll
    for (int k = 0; k < 4; k++) {
        uint32_t ah[4], al[4];
        ldmA(ah, sb + KB_AH + arow + k*32);
        ldmA(al, sb + KB_AL + arow + k*32);
        uint32_t brow = (uint32_t)((k*16 + (lane & 15))*264)*2;
#pragma unroll
        for (int i = 0; i < 8; i++) {
            uint32_t bh[4], bl[4];
            ldmBt(bh, sb + KB_BH + brow + bcol + i*32);
            ldmBt(bl, sb + KB_BL + brow + bcol + i*32);
            mma_bf16(acc[2*i],   ah, bh[0], bh[1]);
            mma_bf16(acc[2*i+1], ah, bh[2], bh[3]);
            mma_bf16(acc[2*i],   al, bh[0], bh[1]);
            mma_bf16(acc[2*i+1], al, bh[2], bh[3]);
            mma_bf16(acc[2*i],   ah, bl[0], bl[1]);
            mma_bf16(acc[2*i+1], ah, bl[2], bl[3]);
        }
    }
    __syncthreads();

    int g = lane >> 2, tig = lane & 3;
#pragma unroll
    for (int a = 0; a < 16; a++) {
        int j0 = nh*128 + a*8 + 2*tig;
        float2 A2 = *(float2*)&gAs[j0];
        float2 B2 = *(float2*)&gBs[j0];
        acc[a][0] = gelu_exact(acc[a][0]*A2.x + B2.x);
        acc[a][1] = gelu_exact(acc[a][1]*A2.y + B2.y);
        acc[a][2] = gelu_exact(acc[a][2]*A2.x + B2.x);
        acc[a][3] = gelu_exact(acc[a][3]*A2.y + B2.y);
    }

    float acc2[2][4];
#pragma unroll
    for (int t = 0; t < 2; t++)
#pragma unroll
        for (int x = 0; x < 4; x++) acc2[t][x] = 0.f;

#pragma unroll
    for (int s = 0; s < 8; s++) {
        uint32_t arh[4], arl[4];
        split2(acc[2*s][0],   acc[2*s][1],   arh[0], arl[0]);
        split2(acc[2*s][2],   acc[2*s][3],   arh[1], arl[1]);
        split2(acc[2*s+1][0], acc[2*s+1][1], arh[2], arl[2]);
        split2(acc[2*s+1][2], acc[2*s+1][3], arh[3], arl[3]);
        uint32_t baddr = (uint32_t)((nh*128 + s*16 + (lane & 15))*16 + (lane >> 4)*8)*2;
        uint32_t brh[4], brl[4];
        ldmBt(brh, sb + KB_W2H + baddr);
        ldmBt(brl, sb + KB_W2L + baddr);
        mma_bf16(acc2[0], arh, brh[0], brh[1]);
        mma_bf16(acc2[1], arh, brh[2], brh[3]);
        mma_bf16(acc2[0], arl, brh[0], brh[1]);
        mma_bf16(acc2[1], arl, brh[2], brh[3]);
        mma_bf16(acc2[0], arh, brl[0], brl[1]);
        mma_bf16(acc2[1], arh, brl[2], brl[3]);
    }

    float* P = (float*)smem;
    int row1 = mt*16 + g, row2 = row1 + 8;
    if (nh == 0) {
#pragma unroll
        for (int t = 0; t < 2; t++) {
            int col = t*8 + 2*tig;
            P[row1*16 + col]     = acc2[t][0];
            P[row1*16 + col + 1] = acc2[t][1];
            P[row2*16 + col]     = acc2[t][2];
            P[row2*16 + col + 1] = acc2[t][3];
        }
    }
    __syncthreads();
    if (nh == 1) {
#pragma unroll
        for (int t = 0; t < 2; t++) {
#pragma unroll
            for (int x = 0; x < 4; x++) {
                int col = t*8 + 2*tig + (x & 1);
                int row = (x < 2) ? row1 : row2;
                if (col < 10)
                    out[((size_t)b*64 + row)*10 + col] = acc2[t][x] + P[row*16 + col] + b2[col];
            }
        }
    }
}

// ---------------- K5: edges via mma.sync (R15 structure) ----------------
#define EG_WFH 0u
#define EG_WFL 46080u
#define EG_ZTH 92160u
#define EG_ZTL 101376u
#define EG_ZAH 110592u
#define EG_ZAL 119808u
#define EG_YH  129024u
#define EG_YL  175104u
#define EG_TOT 221184

__global__ __launch_bounds__(512, 1)
void k_edges_mma(float* __restrict__ out) {
    extern __shared__ char smem[];
    uint32_t sb = smem_u32(smem);
    int tid = threadIdx.x, b = blockIdx.x;
    int lane = tid & 31, w = tid >> 5;

    for (int it = tid; it < 10240; it += 512) {
        int td = it >> 5, c2 = (it & 31)*2;
        uint32_t vh = *(const uint32_t*)&g_Wf_hi[td*64 + c2];
        uint32_t vl = *(const uint32_t*)&g_Wf_lo[td*64 + c2];
        *(uint32_t*)(smem + EG_WFH + (td*72 + c2)*2) = vh;
        *(uint32_t*)(smem + EG_WFL + (td*72 + c2)*2) = vl;
    }
    const __nv_bfloat16* zh = g_z_hi + (size_t)b*4096;
    const __nv_bfloat16* zl = g_z_lo + (size_t)b*4096;
    for (int it = tid; it < 2048; it += 512) {
        int a = it >> 5, c2 = (it & 31)*2;
        uint32_t vh = *(const uint32_t*)&zh[a*64 + c2];
        uint32_t vl = *(const uint32_t*)&zl[a*64 + c2];
        *(uint32_t*)(smem + EG_ZAH + (a*72 + c2)*2) = vh;
        *(uint32_t*)(smem + EG_ZAL + (a*72 + c2)*2) = vl;
        __nv_bfloat162 hv = *reinterpret_cast<__nv_bfloat162*>(&vh);
        __nv_bfloat162 lv = *reinterpret_cast<__nv_bfloat162*>(&vl);
        *(__nv_bfloat16*)(smem + EG_ZTH + (c2*72 + a)*2)     = hv.x;
        *(__nv_bfloat16*)(smem + EG_ZTH + ((c2+1)*72 + a)*2) = hv.y;
        *(__nv_bfloat16*)(smem + EG_ZTL + (c2*72 + a)*2)     = lv.x;
        *(__nv_bfloat16*)(smem + EG_ZTL + ((c2+1)*72 + a)*2) = lv.y;
    }
    __syncthreads();

    // ---- Phase 1: Y[320][64] = Wf @ zT ; 80 m16n16 tiles, 5 per warp ----
#pragma unroll
    for (int r = 0; r < 5; r++) {
        int idx = w*5 + r;
        int mt = idx >> 2, nq = idx & 3;
        float acc[2][4];
#pragma unroll
        for (int t = 0; t < 2; t++)
#pragma unroll
            for (int x = 0; x < 4; x++) acc[t][x] = 0.f;

        uint32_t arow = (uint32_t)((mt*16 + (lane&15))*72 + (lane>>4)*8)*2;
        uint32_t bcol = (uint32_t)(nq*16 + (lane>>4)*8)*2;
#pragma unroll
        for (int k = 0; k < 4; k++) {
            uint32_t ah[4], al[4];
            ldmA(ah, sb + EG_WFH + arow + k*32);
            ldmA(al, sb + EG_WFL + arow + k*32);
            uint32_t brow = (uint32_t)((k*16 + (lane&15))*72)*2;
            uint32_t bh[4], bl[4];
            ldmBt(bh, sb + EG_ZTH + brow + bcol);
            ldmBt(bl, sb + EG_ZTL + brow + bcol);
            mma_bf16(acc[0], ah, bh[0], bh[1]);
            mma_bf16(acc[1], ah, bh[2], bh[3]);
            mma_bf16(acc[0], al, bh[0], bh[1]);
            mma_bf16(acc[1], al, bh[2], bh[3]);
            mma_bf16(acc[0], ah, bl[0], bl[1]);
            mma_bf16(acc[1], ah, bl[2], bl[3]);
        }
        int g = lane >> 2, tig = lane & 3;
#pragma unroll
        for (int t = 0; t < 2; t++) {
            int col = nq*16 + t*8 + 2*tig;
#pragma unroll
            for (int half = 0; half < 2; half++) {
                int row = mt*16 + g + half*8;
                uint32_t hp, lp;
                split2(acc[t][2*half], acc[t][2*half + 1], hp, lp);
                *(uint32_t*)(smem + EG_YH + (row*72 + col)*2) = hp;
                *(uint32_t*)(smem + EG_YL + (row*72 + col)*2) = lp;
            }
        }
    }
    __syncthreads();

    // ---- Phase 2: warp = (molh, i-16-tile, j-8-tile); skip all-dead tiles ----
    {
        int molh = w >> 3, mt2 = (w >> 2) & 1, jn = w & 3;
        if (!(mt2 == 1 && jn < 2)) {
            uint32_t ah[4][4], al[4][4];
            uint32_t off = (uint32_t)(((molh*32 + mt2*16 + (lane&15))*72 + (lane>>4)*8)*2);
#pragma unroll
            for (int k = 0; k < 4; k++) {
                ldmA(ah[k], sb + EG_ZAH + off + k*32);
                ldmA(al[k], sb + EG_ZAL + off + k*32);
            }
            float acc[5][4];
#pragma unroll
            for (int t = 0; t < 5; t++)
#pragma unroll
                for (int x = 0; x < 4; x++) acc[t][x] = 0.f;

            int jcol = molh*32 + jn*8;
#pragma unroll
            for (int t = 0; t < 5; t++) {
#pragma unroll
                for (int k = 0; k < 4; k++) {
                    uint32_t row = (uint32_t)(t*64 + k*16 + (lane & 15));
                    uint32_t bh[2], bl[2];
                    ldmBt2(bh, sb + EG_YH + (row*72 + jcol)*2);
                    ldmBt2(bl, sb + EG_YL + (row*72 + jcol)*2);
                    mma_bf16(acc[t], ah[k], bh[0], bh[1]);
                    mma_bf16(acc[t], al[k], bh[0], bh[1]);
                    mma_bf16(acc[t], ah[k], bl[0], bl[1]);
                }
            }

            int g = lane >> 2, tig = lane & 3;
            int mol = b*2 + molh;
            float* eout = out + ATOM_OUT + mol*(NEDGE*5);
#pragma unroll
            for (int pos = 0; pos < 4; pos++) {
                int i = mt2*16 + g + (pos >> 1)*8;
                int j = jn*8 + 2*tig + (pos & 1);
                if (i < j) {
                    float v0 = acc[0][pos], v1 = acc[1][pos], v2 = acc[2][pos],
                          v3 = acc[3][pos], v4 = acc[4][pos];
                    float m = fmaxf(fmaxf(fmaxf(v0, v1), fmaxf(v2, v3)), v4);
                    float e0 = __expf(v0-m), e1 = __expf(v1-m), e2 = __expf(v2-m),
                          e3 = __expf(v3-m), e4 = __expf(v4-m);
                    float inv = 1.f/(e0+e1+e2+e3+e4);
                    int e = 31*i - (i*(i-1))/2 + (j - i - 1);
                    float* dst = eout + e*5;
                    dst[0] = e0*inv; dst[1] = e1*inv; dst[2] = e2*inv;
                    dst[3] = e3*inv; dst[4] = e4*inv;
                }
            }
        }
    }
}

// ---------------- launch ----------------
extern "C" void kernel_launch(void* const* d_in, const int* in_sizes, int n_in,
                              void* d_out, int out_size) {
    const float* z  = (const float*)d_in[0];
    const float* W1 = (const float*)d_in[1];
    const float* b1 = (const float*)d_in[2];
    const float* gm = (const float*)d_in[3];
    const float* bt = (const float*)d_in[4];
    const float* W2 = (const float*)d_in[5];
    const float* b2 = (const float*)d_in[6];
    const float* bm = (const float*)d_in[7];
    float* out = (float*)d_out;
    (void)in_sizes; (void)n_in; (void)out_size;

    cudaFuncSetAttribute(k_atoms_mma, cudaFuncAttributeMaxDynamicSharedMemorySize, KB_TOT);
    cudaFuncSetAttribute(k_edges_mma, cudaFuncAttributeMaxDynamicSharedMemorySize, EG_TOT);

    k_prep_stats<<<848, 256>>>(z, bm);
    k_reduce    <<<65,  1024>>>();
    k_finalize  <<<64,  256>>>(W1, b1, gm, bt);
    k_atoms_mma <<<512, 256, KB_TOT>>>(W2, b2, out);
    k_edges_mma <<<512, 512, EG_TOT>>>(out);
}